// round 1
// baseline (speedup 1.0000x reference)
#include <cuda_runtime.h>
#include <math.h>

// Problem constants (fixed by the reference: N, M, D, Q = 4096, 4096, 4, 4)
#define NROWS 4096
#define MCOLS 4096
#define QMIX  4
#define DDIM  4
#define NFIELD 13   // fields per (row,q): [0..3]=xs/y, [4..7]=cos, [8..11]=sin, [12]=A

// Scratch feature arrays (field-major: [q][field][row]) — 832KB each.
__device__ float g_xfeat[QMIX * NFIELD * NROWS];
__device__ float g_yfeat[QMIX * NFIELD * MCOLS];

// ---------------------------------------------------------------------------
// Kernel 1: per-row feature precompute (off the hot path; uses accurate
// sincosf/expf). One thread per (row) over x-rows then y-rows.
//
//   For x-row n, mixture q:
//     xs_d = 4*pi^2*log2(e) * v_qd * x_d          (cross-term coefficient)
//     cA_d = cos(2*pi*mu_qd*x_d), sA_d = sin(...)
//     Ax   = log2(w_q) - 2*pi^2*log2(e) * sum_d v_qd x_d^2
//   For y-row m: y_d raw, cB/sB analogous, Ay = -2*pi^2*log2e * sum v y^2.
//
//   Then k(n,m) = sum_q exp2(Ax+Ay+sum_d xs_d*y_d) * prod_d (cA cB + sA sB)
// ---------------------------------------------------------------------------
__global__ void feat_kernel(const float* __restrict__ x, const float* __restrict__ y,
                            const float* __restrict__ lw, const float* __restrict__ mu,
                            const float* __restrict__ lv) {
    int i = blockIdx.x * blockDim.x + threadIdx.x;
    if (i >= NROWS + MCOLS) return;
    const bool isX = (i < NROWS);
    const int n = isX ? i : i - NROWS;
    const float* row = isX ? (x + n * DDIM) : (y + n * DDIM);
    float* out = isX ? g_xfeat : g_yfeat;
    const int L = isX ? NROWS : MCOLS;

    const float TWO_PI = 6.283185307179586f;
    const float C2     = 19.739208802178716f;   // 2*pi^2
    const float LOG2E  = 1.4426950408889634f;

    float r[DDIM];
#pragma unroll
    for (int d = 0; d < DDIM; ++d) r[d] = row[d];

#pragma unroll
    for (int q = 0; q < QMIX; ++q) {
        float sum = 0.f;
#pragma unroll
        for (int d = 0; d < DDIM; ++d) {
            float v = expf(lv[q * DDIM + d]);
            float m = mu[q * DDIM + d];
            float a = TWO_PI * m * r[d];
            float s, c;
            sincosf(a, &s, &c);
            out[(q * NFIELD + 4 + d) * L + n] = c;
            out[(q * NFIELD + 8 + d) * L + n] = s;
            out[(q * NFIELD + d) * L + n] = isX ? (2.f * C2 * LOG2E * v * r[d]) : r[d];
            sum += v * r[d] * r[d];
        }
        float A = -C2 * LOG2E * sum;
        if (isX) A += lw[q] * LOG2E;   // fold log2(weight) into the x side
        out[(q * NFIELD + 12) * L + n] = A;
    }
}

// ---------------------------------------------------------------------------
// Kernel 2: GEMM-style tile kernel. 64x64 output tile per block, 128 threads,
// each thread computes a 4x8 micro-tile (processed as two 4x4 halves to bound
// register pressure). Smem is field-major so every hot load is a
// conflict-free LDS.128.
// ---------------------------------------------------------------------------
__global__ void __launch_bounds__(128)
sm_tile_kernel(float* __restrict__ out) {
    __shared__ float XS[QMIX * NFIELD * 64];   // 13312 B
    __shared__ float YS[QMIX * NFIELD * 64];

    const int rowBase = blockIdx.y * 64;
    const int colBase = blockIdx.x * 64;
    const int tid = threadIdx.x;

    // Cooperative smem fill: 52 segments x 16 float4 per side.
    {
        float4* xs4 = reinterpret_cast<float4*>(XS);
        float4* ys4 = reinterpret_cast<float4*>(YS);
        for (int s = tid; s < QMIX * NFIELD * 16; s += 128) {
            const int seg = s >> 4;      // q*NFIELD + field
            const int j   = s & 15;
            xs4[s] = *reinterpret_cast<const float4*>(&g_xfeat[seg * NROWS + rowBase + j * 4]);
            ys4[s] = *reinterpret_cast<const float4*>(&g_yfeat[seg * MCOLS + colBase + j * 4]);
        }
    }
    __syncthreads();

    const int tx = tid & 7;        // 8 column groups
    const int ty = tid >> 3;       // 16 row groups
    const int r0 = ty * 4;         // 4 rows per thread
    const int c0 = tx * 8;         // 8 cols per thread

    float acc[4][8];
#pragma unroll
    for (int r = 0; r < 4; ++r)
#pragma unroll
        for (int c = 0; c < 8; ++c) acc[r][c] = 0.f;

#pragma unroll 1
    for (int q = 0; q < QMIX; ++q) {
        const float* Xq = XS + q * NFIELD * 64;
        const float* Yq = YS + q * NFIELD * 64;

        // X-side per-row scalars (reused by both column halves)
        float ax[4];
        {
            float4 t = *reinterpret_cast<const float4*>(Xq + 12 * 64 + r0);
            ax[0] = t.x; ax[1] = t.y; ax[2] = t.z; ax[3] = t.w;
        }

#pragma unroll
        for (int h = 0; h < 2; ++h) {          // two 4-column halves
            const int cb_ = c0 + h * 4;

            float ay[4];
            {
                float4 t = *reinterpret_cast<const float4*>(Yq + 12 * 64 + cb_);
                ay[0] = t.x; ay[1] = t.y; ay[2] = t.z; ay[3] = t.w;
            }

            // exp2 argument: Ax + Ay + sum_d xs_d * y_d
            float tv[4][4];
#pragma unroll
            for (int r = 0; r < 4; ++r)
#pragma unroll
                for (int c = 0; c < 4; ++c) tv[r][c] = ax[r] + ay[c];

#pragma unroll
            for (int d = 0; d < 4; ++d) {
                float xs[4], yv[4];
                {
                    float4 t = *reinterpret_cast<const float4*>(Xq + d * 64 + r0);
                    xs[0] = t.x; xs[1] = t.y; xs[2] = t.z; xs[3] = t.w;
                }
                {
                    float4 t = *reinterpret_cast<const float4*>(Yq + d * 64 + cb_);
                    yv[0] = t.x; yv[1] = t.y; yv[2] = t.z; yv[3] = t.w;
                }
#pragma unroll
                for (int r = 0; r < 4; ++r)
#pragma unroll
                    for (int c = 0; c < 4; ++c)
                        tv[r][c] = fmaf(xs[r], yv[c], tv[r][c]);
            }

            // cosine product: prod_d (cA*cB + sA*sB)
            float cp[4][4];
#pragma unroll
            for (int d = 0; d < 4; ++d) {
                float ca[4], sa[4], cbv[4], sbv[4];
                {
                    float4 t = *reinterpret_cast<const float4*>(Xq + (4 + d) * 64 + r0);
                    ca[0] = t.x; ca[1] = t.y; ca[2] = t.z; ca[3] = t.w;
                }
                {
                    float4 t = *reinterpret_cast<const float4*>(Xq + (8 + d) * 64 + r0);
                    sa[0] = t.x; sa[1] = t.y; sa[2] = t.z; sa[3] = t.w;
                }
                {
                    float4 t = *reinterpret_cast<const float4*>(Yq + (4 + d) * 64 + cb_);
                    cbv[0] = t.x; cbv[1] = t.y; cbv[2] = t.z; cbv[3] = t.w;
                }
                {
                    float4 t = *reinterpret_cast<const float4*>(Yq + (8 + d) * 64 + cb_);
                    sbv[0] = t.x; sbv[1] = t.y; sbv[2] = t.z; sbv[3] = t.w;
                }
                if (d == 0) {
#pragma unroll
                    for (int r = 0; r < 4; ++r)
#pragma unroll
                        for (int c = 0; c < 4; ++c)
                            cp[r][c] = fmaf(ca[r], cbv[c], sa[r] * sbv[c]);
                } else {
#pragma unroll
                    for (int r = 0; r < 4; ++r)
#pragma unroll
                        for (int c = 0; c < 4; ++c)
                            cp[r][c] *= fmaf(ca[r], cbv[c], sa[r] * sbv[c]);
                }
            }

            // accumulate: acc += exp2(t) * cosprod   (weight folded into Ax)
#pragma unroll
            for (int r = 0; r < 4; ++r)
#pragma unroll
                for (int c = 0; c < 4; ++c)
                    acc[r][c + h * 4] = fmaf(exp2f(tv[r][c]), cp[r][c], acc[r][c + h * 4]);
        }
    }

    // Store 4x8 micro-tile as two float4 per row.
#pragma unroll
    for (int r = 0; r < 4; ++r) {
        const size_t base = (size_t)(rowBase + r0 + r) * MCOLS + colBase + c0;
        float4 v0 = make_float4(acc[r][0], acc[r][1], acc[r][2], acc[r][3]);
        float4 v1 = make_float4(acc[r][4], acc[r][5], acc[r][6], acc[r][7]);
        *reinterpret_cast<float4*>(&out[base])     = v0;
        *reinterpret_cast<float4*>(&out[base + 4]) = v1;
    }
}

extern "C" void kernel_launch(void* const* d_in, const int* in_sizes, int n_in,
                              void* d_out, int out_size) {
    const float* x  = (const float*)d_in[0];
    const float* y  = (const float*)d_in[1];
    const float* lw = (const float*)d_in[2];
    const float* mu = (const float*)d_in[3];
    const float* lv = (const float*)d_in[4];
    float* out = (float*)d_out;

    (void)in_sizes; (void)n_in; (void)out_size;

    feat_kernel<<<(NROWS + MCOLS + 255) / 256, 256>>>(x, y, lw, mu, lv);

    dim3 grid(MCOLS / 64, NROWS / 64);
    sm_tile_kernel<<<grid, 128>>>(out);
}